// round 10
// baseline (speedup 1.0000x reference)
#include <cuda_runtime.h>
#include <cstdint>

#define B_    16
#define T_    4096
#define DIM_  256
#define H_    128
#define G3    384
#define BT    65536   // B_*T_
#define CHUNK 128
#define NCHUNK 32     // T_/CHUNK
#define NMT   512     // BT/128 m-tiles
#define NNT   4       // 384/96 n-tiles
#define TICKETS (2*NMT*NNT)  // 4096 per layer
#define SPIN_CAP (1u << 21)  // bounded spins: bug -> wrong answer, not hang

// Scratch: two xg buffers (layer parity), two activation buffers, sync state.
__device__ float g_xg[2][2ull * BT * G3];       // 2 x 201 MB
__device__ float g_buf[2][(size_t)BT * DIM_];   // 2 x 64 MB
__device__ int g_tileflag[3][2][NMT];           // n-tiles done per (l,d,mtile)
__device__ int g_prog[3][2][B_];                // rnn steps done per (l,d,b)
__device__ int g_ticket[3];                     // gemm work queue heads

typedef unsigned long long ull;

__device__ __forceinline__ ull ffma2(ull a, ull b, ull c) {
    ull d;
    asm("fma.rn.f32x2 %0, %1, %2, %3;" : "=l"(d) : "l"(a), "l"(b), "l"(c));
    return d;
}
__device__ __forceinline__ ull fpack2(float lo, float hi) {
    ull r;
    asm("mov.b64 %0, {%1, %2};" : "=l"(r) : "f"(lo), "f"(hi));
    return r;
}
__device__ __forceinline__ float2 funpack(ull v) {
    float2 r;
    asm("mov.b64 {%0, %1}, %2;" : "=f"(r.x), "=f"(r.y) : "l"(v));
    return r;
}
__device__ __forceinline__ float sigmoidf_fast(float x) {
    return __fdividef(1.0f, 1.0f + __expf(-x));
}
__device__ __forceinline__ float tanhf_fast(float x) {
    return __fdividef(2.0f, 1.0f + __expf(-2.0f * x)) - 1.0f;
}
__device__ __forceinline__ void spin_ge(volatile int* p, int need, int ns) {
    unsigned it = 0;
    while (*p < need && ++it < SPIN_CAP) __nanosleep(ns);
}

__global__ void init_sync() {
    int i = blockIdx.x * blockDim.x + threadIdx.x;
    if (i < 3 * 2 * NMT) ((int*)g_tileflag)[i] = 0;
    if (i < 3 * 2 * B_) ((int*)g_prog)[i] = 0;
    if (i < 3) g_ticket[i] = 0;
}

// ---------------------------------------------------------------------------
// Fused persistent kernel, 128 threads/CTA everywhere.
// Blocks 0..31: recurrence chain (b,d). Thread t owns ALL THREE gate columns
// {t, 128+t, 256+t} of Wh in registers (192 regs; cap at 128 thr is 512).
// Everything is thread-local after the dot: r, z, n, h-update. Ping-pong h
// buffers make ONE barrier per step sufficient:
//   step t reads h from buf[t&1] (all reads pre-bar of step t),
//   writes h_{t+1} to buf[(t&1)^1] (prev readers of that buf synced at the
//   bar ending step t-1). No rr/zz exchange at all.
// Blocks 32..147: gemm workers producing xg tiles from a ticket queue.
// ---------------------------------------------------------------------------
__global__ void __launch_bounds__(128, 1) mega(const float* __restrict__ xin,
                                               const float* __restrict__ Wi,
                                               const float* __restrict__ Wh,
                                               const float* __restrict__ bh,
                                               float* __restrict__ out) {
    const int tid = threadIdx.x;

    if (blockIdx.x < 32) {
        // =================== recurrence CTA: chain (b,d) ===================
        const int b = blockIdx.x & 15;
        const int d = blockIdx.x >> 4;

        __shared__ __align__(16) float h_s[2][H_];  // ping-pong h

        const int sd = d ? -1 : 1;
        const long xstep = (long)sd * G3;
        const long ystep = (long)sd * DIM_;

        for (int l = 0; l < 3; l++) {
            float* __restrict__ Y = (l == 2) ? out : g_buf[l];
            const float* __restrict__ W = Wh + (size_t)(l * 2 + d) * H_ * G3;
            const float* __restrict__ xgb =
                g_xg[l & 1] + ((size_t)d * BT + (size_t)b * T_) * G3;

            // Thread t's three full columns, f32x2-packed along k.
            ull wr[64], wz[64], wn[64];
            {
                const float* Wr = W + tid;
                const float* Wz = W + 128 + tid;
                const float* Wn = W + 256 + tid;
#pragma unroll
                for (int j = 0; j < 64; j++) {
                    wr[j] = fpack2(Wr[(size_t)(2 * j) * G3],
                                   Wr[(size_t)(2 * j + 1) * G3]);
                    wz[j] = fpack2(Wz[(size_t)(2 * j) * G3],
                                   Wz[(size_t)(2 * j + 1) * G3]);
                    wn[j] = fpack2(Wn[(size_t)(2 * j) * G3],
                                   Wn[(size_t)(2 * j + 1) * G3]);
                }
            }
            const float* bbase = bh + (size_t)(l * 2 + d) * G3;
            const float bias_r = bbase[tid];
            const float bias_z = bbase[128 + tid];
            const float bias_n = bbase[256 + tid];

            h_s[0][tid] = 0.0f;
            h_s[1][tid] = 0.0f;
            float hold = 0.0f;

            const float* xp = xgb + (d ? (size_t)(T_ - 1) * G3 : 0) + tid;
            float* yp = Y + (size_t)b * T_ * DIM_ + d * H_ + tid +
                        (d ? (size_t)(T_ - 1) * DIM_ : 0);

            if (tid == 0) {
                int tc0 = d ? (NCHUNK - 1) : 0;
                spin_ge(&g_tileflag[l][d][b * NCHUNK + tc0], NNT, 128);
                __threadfence();
            }
            __syncthreads();
            float xr = xp[0] + bias_r;
            float xz = xp[128] + bias_z;
            float xn = xp[256];
            xp += xstep;

            for (int c = 0; c < NCHUNK; c++) {
                if (tid == 0 && c + 1 < NCHUNK) {
                    int tcn = d ? (NCHUNK - 2 - c) : (c + 1);
                    spin_ge(&g_tileflag[l][d][b * NCHUNK + tcn], NNT, 128);
                    __threadfence();
                }
                __syncthreads();

#pragma unroll 1
                for (int t2 = 0; t2 < CHUNK; t2++) {
                    // Three full dots (one per gate) over h (broadcast LDS).
                    const ulonglong2* hp = (const ulonglong2*)h_s[t2 & 1];
                    ull ar0 = 0, ar1 = 0, az0 = 0, az1 = 0, an0 = 0, an1 = 0;
#pragma unroll
                    for (int j = 0; j < 32; j++) {
                        ulonglong2 hv = hp[j];
                        ar0 = ffma2(wr[2 * j], hv.x, ar0);
                        ar1 = ffma2(wr[2 * j + 1], hv.y, ar1);
                        az0 = ffma2(wz[2 * j], hv.x, az0);
                        az1 = ffma2(wz[2 * j + 1], hv.y, az1);
                        an0 = ffma2(wn[2 * j], hv.x, an0);
                        an1 = ffma2(wn[2 * j + 1], hv.y, an1);
                    }
                    // Prefetch next step's xg (one-past-end stays in g_xg).
                    float nxr = xp[0] + bias_r;
                    float nxz = xp[128] + bias_z;
                    float nxn = xp[256];
                    xp += xstep;

                    float2 a, bb;
                    a = funpack(ar0); bb = funpack(ar1);
                    float dr = (a.x + a.y) + (bb.x + bb.y);
                    a = funpack(az0); bb = funpack(az1);
                    float dz = (a.x + a.y) + (bb.x + bb.y);
                    a = funpack(an0); bb = funpack(an1);
                    float dn = (a.x + a.y) + (bb.x + bb.y);

                    // Fully thread-local gate math.
                    float r = sigmoidf_fast(xr + dr);
                    float z = sigmoidf_fast(xz + dz);
                    float n = tanhf_fast(fmaf(r, dn + bias_n, xn));
                    float hnew = fmaf(z, hold - n, n);
                    h_s[(t2 & 1) ^ 1][tid] = hnew;   // write OTHER buffer
                    hold = hnew;
                    *yp = hnew;
                    yp += ystep;
                    __syncthreads();  // the ONLY per-step barrier
                    xr = nxr; xz = nxz; xn = nxn;
                }

                // Publish progress (release: fence -> bar -> flag).
                __threadfence();
                __syncthreads();
                if (tid == 0) atomicExch(&g_prog[l][d][b], (c + 1) * CHUNK);
            }
            __syncthreads();
        }
    } else {
        // ======================= gemm worker CTA (128 thr) =================
        // xg[l][d][bt][c] = sum_k X[bt][k] * Wi[l][d][k][c]
        // BM=128, BN=96, BK=16; 16x8 thread grid, 8x12 micro-tile.
        __shared__ __align__(16) float As[16][128];
        __shared__ __align__(16) float Bs[16][96];
        __shared__ int sh_tk;

        const int bk = tid >> 3;            // B fill k-row 0..15
        const int bc = (tid & 7) * 12;      // B fill col (12 wide)
        const int ry = (tid >> 3) * 8;      // micro rows
        const int cx = (tid & 7) * 12;      // micro cols

        for (int l = 0; l < 3; l++) {
            const float* __restrict__ X = (l == 0) ? xin : g_buf[l - 1];
            float* __restrict__ Cb = g_xg[l & 1];

            while (true) {
                if (tid == 0) sh_tk = atomicAdd(&g_ticket[l], 1);
                __syncthreads();
                int tk = sh_tk;
                if (tk >= TICKETS) break;

                // Decode ticket -> (tc, d, b, nt). Layer 0: ends-first tc
                // order (matches rnn consumption); layers 1-2: middle-out.
                int i = tk >> 7;       // 0..31
                int rem = tk & 127;
                int tc;
                if (l == 0) {
                    tc = (i & 1) ? (31 - (i >> 1)) : (i >> 1);
                } else {
                    tc = (i & 1) ? (16 + (i >> 1)) : (15 - (i >> 1));
                }
                int d = rem >> 6;
                int b = (rem >> 2) & 15;
                int nt = rem & 3;
                int m = b * NCHUNK + tc;

                // Gate on upstream recurrence progress (acquire).
                if (l > 0) {
                    if (tid == 0) {
                        spin_ge(&g_prog[l - 1][0][b], (tc + 1) * CHUNK, 256);
                        spin_ge(&g_prog[l - 1][1][b], T_ - tc * CHUNK, 256);
                        __threadfence();
                    }
                    __syncthreads();
                }

                const int m0 = m * 128;
                const int n0 = nt * 96;
                const float* __restrict__ W =
                    Wi + (size_t)(l * 2 + d) * DIM_ * G3;
                float* __restrict__ C = Cb + (size_t)d * BT * G3;

                const float* Ap = X + (size_t)(m0 + tid) * DIM_;  // own row
                const float* Bp = W + (size_t)bk * G3 + n0 + bc;

                float acc[8][12];
#pragma unroll
                for (int ii = 0; ii < 8; ii++)
#pragma unroll
                    for (int jj = 0; jj < 12; jj++) acc[ii][jj] = 0.0f;

                // Prefetch first tile.
                float4 a0 = *(const float4*)(Ap + 0);
                float4 a1 = *(const float4*)(Ap + 4);
                float4 a2 = *(const float4*)(Ap + 8);
                float4 a3 = *(const float4*)(Ap + 12);
                float4 b0 = *(const float4*)(Bp + 0);
                float4 b1 = *(const float4*)(Bp + 4);
                float4 b2 = *(const float4*)(Bp + 8);

#pragma unroll 1
                for (int k0 = 0; k0 < DIM_; k0 += 16) {
                    // Commit prefetched tile (A transposed: As[k][row]).
                    As[0][tid] = a0.x;  As[1][tid] = a0.y;
                    As[2][tid] = a0.z;  As[3][tid] = a0.w;
                    As[4][tid] = a1.x;  As[5][tid] = a1.y;
                    As[6][tid] = a1.z;  As[7][tid] = a1.w;
                    As[8][tid] = a2.x;  As[9][tid] = a2.y;
                    As[10][tid] = a2.z; As[11][tid] = a2.w;
                    As[12][tid] = a3.x; As[13][tid] = a3.y;
                    As[14][tid] = a3.z; As[15][tid] = a3.w;
                    *(float4*)&Bs[bk][bc] = b0;
                    *(float4*)&Bs[bk][bc + 4] = b1;
                    *(float4*)&Bs[bk][bc + 8] = b2;
                    __syncthreads();

                    if (k0 + 16 < DIM_) {
                        a0 = *(const float4*)(Ap + k0 + 16);
                        a1 = *(const float4*)(Ap + k0 + 20);
                        a2 = *(const float4*)(Ap + k0 + 24);
                        a3 = *(const float4*)(Ap + k0 + 28);
                        b0 = *(const float4*)(Bp + (size_t)(k0 + 16) * G3);
                        b1 = *(const float4*)(Bp + (size_t)(k0 + 16) * G3 + 4);
                        b2 = *(const float4*)(Bp + (size_t)(k0 + 16) * G3 + 8);
                    }

#pragma unroll
                    for (int k = 0; k < 16; k++) {
                        float4 av0 = *(const float4*)&As[k][ry];
                        float4 av1 = *(const float4*)&As[k][ry + 4];
                        float4 bv0 = *(const float4*)&Bs[k][cx];
                        float4 bv1 = *(const float4*)&Bs[k][cx + 4];
                        float4 bv2 = *(const float4*)&Bs[k][cx + 8];
                        float a[8] = {av0.x, av0.y, av0.z, av0.w,
                                      av1.x, av1.y, av1.z, av1.w};
                        float bbv[12] = {bv0.x, bv0.y, bv0.z, bv0.w,
                                         bv1.x, bv1.y, bv1.z, bv1.w,
                                         bv2.x, bv2.y, bv2.z, bv2.w};
#pragma unroll
                        for (int ii = 0; ii < 8; ii++)
#pragma unroll
                            for (int jj = 0; jj < 12; jj++)
                                acc[ii][jj] = fmaf(a[ii], bbv[jj], acc[ii][jj]);
                    }
                    __syncthreads();
                }

#pragma unroll
                for (int ii = 0; ii < 8; ii++) {
                    float* crow = C + (size_t)(m0 + ry + ii) * G3 + n0 + cx;
                    *(float4*)(crow) =
                        make_float4(acc[ii][0], acc[ii][1], acc[ii][2], acc[ii][3]);
                    *(float4*)(crow + 4) =
                        make_float4(acc[ii][4], acc[ii][5], acc[ii][6], acc[ii][7]);
                    *(float4*)(crow + 8) =
                        make_float4(acc[ii][8], acc[ii][9], acc[ii][10], acc[ii][11]);
                }

                // Publish tile (release).
                __threadfence();
                __syncthreads();
                if (tid == 0) atomicAdd(&g_tileflag[l][d][m], 1);
            }
        }
    }
}

// ---------------------------------------------------------------------------
extern "C" void kernel_launch(void* const* d_in, const int* in_sizes, int n_in,
                              void* d_out, int out_size) {
    (void)in_sizes;
    (void)n_in;
    (void)out_size;
    const float* x = (const float*)d_in[0];    // [16,4096,256]
    const float* Wi = (const float*)d_in[1];   // [3,2,256,384]
    const float* Wh = (const float*)d_in[2];   // [3,2,128,384]
    const float* bh = (const float*)d_in[3];   // [3,2,384]
    float* out = (float*)d_out;                // [16,4096,256]

    init_sync<<<13, 256>>>();
    mega<<<148, 128>>>(x, Wi, Wh, bh, out);
}